// round 1
// baseline (speedup 1.0000x reference)
#include <cuda_runtime.h>
#include <math.h>

#define NNODES 50000
#define NEDGES 1600000

// ---------------- scratch (static device globals; no allocation) ----------------
__device__ float g_bufA[(size_t)NNODES * 2000];   // 400 MB
__device__ float g_bufB[(size_t)NNODES * 2000];   // 400 MB
__device__ float g_bufS0[NNODES * 10];
__device__ float g_bufS1[NNODES * 10];
__device__ int   g_rowptr[NNODES + 1];
__device__ int   g_cursor[NNODES + 1];
__device__ int   g_cols[NEDGES];
__device__ float g_vals[NEDGES];

// ---------------- CSR build (rebuilt every launch; deterministic inputs) --------
__global__ void k_zero_counts() {
    for (int i = blockIdx.x * blockDim.x + threadIdx.x; i <= NNODES;
         i += gridDim.x * blockDim.x)
        g_cursor[i] = 0;
}

__global__ void k_hist(const int* __restrict__ row) {
    for (int e = blockIdx.x * blockDim.x + threadIdx.x; e < NEDGES;
         e += gridDim.x * blockDim.x)
        atomicAdd(&g_cursor[row[e]], 1);
}

__global__ void k_scan() {  // single block, 1024 threads
    __shared__ int s[1024];
    const int CH = (NNODES + 1023) / 1024;  // 49
    int t = threadIdx.x;
    int beg = t * CH;
    int end = min(NNODES, beg + CH);
    int mysum = 0;
    for (int i = beg; i < end; i++) mysum += g_cursor[i];
    s[t] = mysum;
    __syncthreads();
    for (int off = 1; off < 1024; off <<= 1) {
        int v = (t >= off) ? s[t - off] : 0;
        __syncthreads();
        s[t] += v;
        __syncthreads();
    }
    int run = s[t] - mysum;  // exclusive prefix
    for (int i = beg; i < end; i++) {
        g_rowptr[i] = run;
        run += g_cursor[i];
    }
    if (t == 1023) g_rowptr[NNODES] = s[1023];
}

__global__ void k_reset_cursor() {
    for (int i = blockIdx.x * blockDim.x + threadIdx.x; i <= NNODES;
         i += gridDim.x * blockDim.x)
        g_cursor[i] = g_rowptr[i];
}

__global__ void k_scatter(const int* __restrict__ row, const int* __restrict__ col,
                          const float* __restrict__ vals) {
    for (int e = blockIdx.x * blockDim.x + threadIdx.x; e < NEDGES;
         e += gridDim.x * blockDim.x) {
        int p = atomicAdd(&g_cursor[row[e]], 1);
        g_cols[p] = col[e];
        g_vals[p] = vals[e];
    }
}

// ---------------- fp32 tiled SGEMM: C[M,N] = op(A)[M,K] @ B[K,N] ----------------
// op(A) = mixA ? 0.5*(A + Amix) : A.  Optional relu on store.
__global__ void __launch_bounds__(256)
k_sgemm(const float* __restrict__ A, const float* __restrict__ Amix,
        const float* __restrict__ B, float* __restrict__ C,
        int M, int N, int K, int mixA, int reluOut) {
    const int BM = 128, BN = 128, BK = 8;
    __shared__ float As[BK][BM];
    __shared__ float Bs[BK][BN];
    int tid = threadIdx.x;
    int tx = tid & 15, ty = tid >> 4;
    int rowBase = blockIdx.y * BM, colBase = blockIdx.x * BN;

    float acc[8][8];
#pragma unroll
    for (int i = 0; i < 8; i++)
#pragma unroll
        for (int j = 0; j < 8; j++) acc[i][j] = 0.f;

    int aRow = tid >> 1;
    int aK = (tid & 1) * 4;
    int bK = tid >> 5;
    int bCol = (tid & 31) * 4;
    int gr = rowBase + aRow;

    for (int k0 = 0; k0 < K; k0 += BK) {
        // A tile (K is always a multiple of 4 here; zero-pad out-of-range)
        {
            int gk = k0 + aK;
            float4 va = make_float4(0.f, 0.f, 0.f, 0.f);
            if (gr < M && gk < K) {
                va = *(const float4*)(A + (size_t)gr * K + gk);
                if (mixA) {
                    float4 w = *(const float4*)(Amix + (size_t)gr * K + gk);
                    va.x = 0.5f * (va.x + w.x);
                    va.y = 0.5f * (va.y + w.y);
                    va.z = 0.5f * (va.z + w.z);
                    va.w = 0.5f * (va.w + w.w);
                }
            }
            As[aK + 0][aRow] = va.x;
            As[aK + 1][aRow] = va.y;
            As[aK + 2][aRow] = va.z;
            As[aK + 3][aRow] = va.w;
        }
        // B tile
        {
            int gk = k0 + bK;
            int gc = colBase + bCol;
            float4 vb = make_float4(0.f, 0.f, 0.f, 0.f);
            if (gk < K) {
                if (gc + 3 < N) {
                    vb = *(const float4*)(B + (size_t)gk * N + gc);
                } else {
                    if (gc + 0 < N) vb.x = B[(size_t)gk * N + gc + 0];
                    if (gc + 1 < N) vb.y = B[(size_t)gk * N + gc + 1];
                    if (gc + 2 < N) vb.z = B[(size_t)gk * N + gc + 2];
                }
            }
            *(float4*)&Bs[bK][bCol] = vb;
        }
        __syncthreads();
#pragma unroll
        for (int kk = 0; kk < BK; kk++) {
            float a[8], b[8];
            *(float4*)&a[0] = *(const float4*)&As[kk][ty * 8];
            *(float4*)&a[4] = *(const float4*)&As[kk][ty * 8 + 4];
            *(float4*)&b[0] = *(const float4*)&Bs[kk][tx * 8];
            *(float4*)&b[4] = *(const float4*)&Bs[kk][tx * 8 + 4];
#pragma unroll
            for (int i = 0; i < 8; i++)
#pragma unroll
                for (int j = 0; j < 8; j++) acc[i][j] += a[i] * b[j];
        }
        __syncthreads();
    }
#pragma unroll
    for (int i = 0; i < 8; i++) {
        int r = rowBase + ty * 8 + i;
        if (r >= M) continue;
        float* crow = C + (size_t)r * N;
#pragma unroll
        for (int j = 0; j < 8; j++) {
            int c = colBase + tx * 8 + j;
            if (c < N) {
                float v = acc[i][j];
                if (reluOut) v = fmaxf(v, 0.f);
                crow[c] = v;
            }
        }
    }
}

// ---------------- SpMM width-500: out[r,:] = sum_e val * in[col,:] ---------------
__global__ void __launch_bounds__(128)
k_spmm_w500(const float* __restrict__ Min, float* __restrict__ Mout, int relu) {
    const int W = 500;
    int r = blockIdx.x;
    int t = threadIdx.x;  // 128
    int start = g_rowptr[r], end = g_rowptr[r + 1];
    float a0 = 0.f, a1 = 0.f, a2 = 0.f, a3 = 0.f;
    __shared__ int scol[128];
    __shared__ float sval[128];
    for (int e0 = start; e0 < end; e0 += 128) {
        int n = min(128, end - e0);
        if (t < n) {
            scol[t] = g_cols[e0 + t];
            sval[t] = g_vals[e0 + t];
        }
        __syncthreads();
        for (int i = 0; i < n; i++) {
            const float* p = Min + (size_t)scol[i] * W;
            float v = sval[i];
            a0 += v * p[t];
            a1 += v * p[t + 128];
            a2 += v * p[t + 256];
            if (t < 116) a3 += v * p[t + 384];
        }
        __syncthreads();
    }
    if (relu) {
        a0 = fmaxf(a0, 0.f);
        a1 = fmaxf(a1, 0.f);
        a2 = fmaxf(a2, 0.f);
        a3 = fmaxf(a3, 0.f);
    }
    float* o = Mout + (size_t)r * W;
    o[t] = a0;
    o[t + 128] = a1;
    o[t + 256] = a2;
    if (t < 116) o[t + 384] = a3;
}

// ---------------- SpMM width-10 (thread per row) --------------------------------
__global__ void k_spmm_w10(const float* __restrict__ Min, float* __restrict__ Mout,
                           int relu) {
    int r = blockIdx.x * blockDim.x + threadIdx.x;
    if (r >= NNODES) return;
    float acc[10];
#pragma unroll
    for (int j = 0; j < 10; j++) acc[j] = 0.f;
    int start = g_rowptr[r], end = g_rowptr[r + 1];
    for (int e = start; e < end; e++) {
        int c = g_cols[e];
        float v = g_vals[e];
        const float2* p = (const float2*)(Min + (size_t)c * 10);
#pragma unroll
        for (int j = 0; j < 5; j++) {
            float2 x = p[j];
            acc[2 * j + 0] += v * x.x;
            acc[2 * j + 1] += v * x.y;
        }
    }
    float* o = Mout + (size_t)r * 10;
#pragma unroll
    for (int j = 0; j < 10; j++) o[j] = relu ? fmaxf(acc[j], 0.f) : acc[j];
}

// ---------------- elementwise mix: O = 0.5*(A+B), n multiple of 4 ----------------
__global__ void k_mix(const float* __restrict__ A, const float* __restrict__ B,
                      float* __restrict__ O, int n4) {
    for (int i = blockIdx.x * blockDim.x + threadIdx.x; i < n4;
         i += gridDim.x * blockDim.x) {
        float4 a = ((const float4*)A)[i];
        float4 b = ((const float4*)B)[i];
        float4 o;
        o.x = 0.5f * (a.x + b.x);
        o.y = 0.5f * (a.y + b.y);
        o.z = 0.5f * (a.z + b.z);
        o.w = 0.5f * (a.w + b.w);
        ((float4*)O)[i] = o;
    }
}

// ---------------- thin GEMM layer4: (0.5*(H+tra3))[50000,2000] @ W4[2000,10] -----
__global__ void __launch_bounds__(256)
k_gemm_thin(const float* __restrict__ Hin, const float* __restrict__ Tmix,
            const float* __restrict__ W4, float* __restrict__ Mout) {
    const int K = 2000, CHUNK = 1000;
    __shared__ float Ws[CHUNK * 10];  // 40 KB
    int tid = threadIdx.x;
    int r = blockIdx.x * 256 + tid;
    float acc[10];
#pragma unroll
    for (int j = 0; j < 10; j++) acc[j] = 0.f;
    for (int k0 = 0; k0 < K; k0 += CHUNK) {
        __syncthreads();
        for (int i = tid; i < CHUNK * 10; i += 256) Ws[i] = W4[k0 * 10 + i];
        __syncthreads();
        if (r < NNODES) {
            const float* hrow = Hin + (size_t)r * K + k0;
            const float* trow = Tmix + (size_t)r * K + k0;
            for (int k = 0; k < CHUNK; k += 4) {
                float4 h = *(const float4*)(hrow + k);
                float4 t = *(const float4*)(trow + k);
                float a0 = 0.5f * (h.x + t.x);
                float a1 = 0.5f * (h.y + t.y);
                float a2 = 0.5f * (h.z + t.z);
                float a3 = 0.5f * (h.w + t.w);
#pragma unroll
                for (int j = 0; j < 10; j++)
                    acc[j] += a0 * Ws[(k + 0) * 10 + j] + a1 * Ws[(k + 1) * 10 + j] +
                              a2 * Ws[(k + 2) * 10 + j] + a3 * Ws[(k + 3) * 10 + j];
            }
        }
    }
    if (r < NNODES) {
        float* o = Mout + (size_t)r * 10;
#pragma unroll
        for (int j = 0; j < 10; j++) o[j] = acc[j];
    }
}

// ---------------- tiny GEMM layer5: (0.5*(H+z))[*,10] @ W5[10,10] ----------------
__global__ void k_gemm5(const float* __restrict__ Hin, const float* __restrict__ Zmix,
                        const float* __restrict__ W5, float* __restrict__ Mout) {
    __shared__ float Ws[100];
    int t = threadIdx.x;
    if (t < 100) Ws[t] = W5[t];
    __syncthreads();
    int r = blockIdx.x * blockDim.x + t;
    if (r >= NNODES) return;
    float a[10];
#pragma unroll
    for (int k = 0; k < 10; k++)
        a[k] = 0.5f * (Hin[(size_t)r * 10 + k] + Zmix[(size_t)r * 10 + k]);
    float* o = Mout + (size_t)r * 10;
#pragma unroll
    for (int j = 0; j < 10; j++) {
        float s = 0.f;
#pragma unroll
        for (int k = 0; k < 10; k++) s += a[k] * Ws[k * 10 + j];
        o[j] = s;
    }
}

// ---------------- row softmax over width 10 --------------------------------------
__global__ void k_softmax(const float* __restrict__ S, float* __restrict__ out) {
    int r = blockIdx.x * blockDim.x + threadIdx.x;
    if (r >= NNODES) return;
    float v[10];
    float m = -1e30f;
#pragma unroll
    for (int j = 0; j < 10; j++) {
        v[j] = S[(size_t)r * 10 + j];
        m = fmaxf(m, v[j]);
    }
    float sum = 0.f;
#pragma unroll
    for (int j = 0; j < 10; j++) {
        v[j] = expf(v[j] - m);
        sum += v[j];
    }
    float inv = 1.f / sum;
#pragma unroll
    for (int j = 0; j < 10; j++) out[(size_t)r * 10 + j] = v[j] * inv;
}

// ---------------- launch ---------------------------------------------------------
extern "C" void kernel_launch(void* const* d_in, const int* in_sizes, int n_in,
                              void* d_out, int out_size) {
    const float* x    = (const float*)d_in[0];   // [50000,512]
    const float* tra1 = (const float*)d_in[1];   // [50000,500]
    const float* tra2 = (const float*)d_in[2];   // [50000,500]
    const float* tra3 = (const float*)d_in[3];   // [50000,2000]
    const float* z    = (const float*)d_in[4];   // [50000,10]
    const float* evals = (const float*)d_in[5];  // [E]
    const int*   row  = (const int*)d_in[6];     // [E]
    const int*   col  = (const int*)d_in[7];     // [E]
    const float* W1 = (const float*)d_in[8];     // [512,500]
    const float* W2 = (const float*)d_in[9];     // [500,500]
    const float* W3 = (const float*)d_in[10];    // [500,2000]
    const float* W4 = (const float*)d_in[11];    // [2000,10]
    const float* W5 = (const float*)d_in[12];    // [10,10]
    float* out = (float*)d_out;

    float *bufA, *bufB, *bufS0, *bufS1;
    cudaGetSymbolAddress((void**)&bufA, g_bufA);
    cudaGetSymbolAddress((void**)&bufB, g_bufB);
    cudaGetSymbolAddress((void**)&bufS0, g_bufS0);
    cudaGetSymbolAddress((void**)&bufS1, g_bufS1);

    // CSR build
    k_zero_counts<<<64, 256>>>();
    k_hist<<<2048, 256>>>(row);
    k_scan<<<1, 1024>>>();
    k_reset_cursor<<<64, 256>>>();
    k_scatter<<<2048, 256>>>(row, col, evals);

    dim3 g500(4, 391), g2000(16, 391);

    // L1: B1 = x @ W1 ; H1 = relu(spmm(B1))
    k_sgemm<<<g500, 256>>>(x, x, W1, bufA, NNODES, 500, 512, 0, 0);
    k_spmm_w500<<<NNODES, 128>>>(bufA, bufB, 1);

    // L2: B2 = (0.5*(H1+tra1)) @ W2 ; H2 = relu(spmm(B2))
    k_sgemm<<<g500, 256>>>(bufB, tra1, W2, bufA, NNODES, 500, 500, 1, 0);
    k_spmm_w500<<<NNODES, 128>>>(bufA, bufB, 1);

    // L3 (reordered: spmm first at width 500, then GEMM to 2000):
    // M3 = 0.5*(H2+tra2) ; S3 = spmm(M3) ; H3 = relu(S3 @ W3)
    k_mix<<<2048, 256>>>(bufB, tra2, bufA, NNODES * 500 / 4);
    k_spmm_w500<<<NNODES, 128>>>(bufA, bufB, 0);
    k_sgemm<<<g2000, 256>>>(bufB, bufB, W3, bufA, NNODES, 2000, 500, 0, 1);

    // L4: B4 = (0.5*(H3+tra3)) @ W4 ; H4 = relu(spmm10(B4))
    k_gemm_thin<<<(NNODES + 255) / 256, 256>>>(bufA, tra3, W4, bufS0);
    k_spmm_w10<<<(NNODES + 255) / 256, 256>>>(bufS0, bufS1, 1);

    // L5: B5 = (0.5*(H4+z)) @ W5 ; S5 = spmm10(B5) ; out = softmax(S5)
    k_gemm5<<<(NNODES + 255) / 256, 256>>>(bufS1, z, W5, bufS0);
    k_spmm_w10<<<(NNODES + 255) / 256, 256>>>(bufS0, bufS1, 0);
    k_softmax<<<(NNODES + 255) / 256, 256>>>(bufS1, out);
}

// round 5
// speedup vs baseline: 1.0466x; 1.0466x over previous
#include <cuda_runtime.h>
#include <math.h>

#define NNODES 50000
#define NEDGES 1600000

// ---------------- scratch (static device globals; no allocation) ----------------
__device__ float g_bufA[(size_t)NNODES * 2000];   // 400 MB
__device__ float g_bufB[(size_t)NNODES * 2000];   // 400 MB
__device__ float g_bufS0[NNODES * 10];
__device__ float g_bufS1[NNODES * 10];
__device__ int   g_rowptr[NNODES + 1];
__device__ int   g_cursor[NNODES + 1];
__device__ int   g_cols[NEDGES];
__device__ float g_vals[NEDGES];

// packed fp32x2 FMA (FFMA2) — ptxas never emits this from C++; 2x fp32 rate
__device__ __forceinline__ void ffma2(float2& d, const float2& a, const float2& b) {
    asm("fma.rn.f32x2 %0, %1, %2, %0;"
        : "+l"(*reinterpret_cast<unsigned long long*>(&d))
        : "l"(*reinterpret_cast<const unsigned long long*>(const_cast<float2*>(&a))),
          "l"(*reinterpret_cast<const unsigned long long*>(const_cast<float2*>(&b))));
}

// ---------------- CSR build (rebuilt every launch; deterministic inputs) --------
__global__ void k_zero_counts() {
    for (int i = blockIdx.x * blockDim.x + threadIdx.x; i <= NNODES;
         i += gridDim.x * blockDim.x)
        g_cursor[i] = 0;
}

__global__ void k_hist(const int* __restrict__ row) {
    for (int e = blockIdx.x * blockDim.x + threadIdx.x; e < NEDGES;
         e += gridDim.x * blockDim.x)
        atomicAdd(&g_cursor[row[e]], 1);
}

__global__ void k_scan() {  // single block, 1024 threads
    __shared__ int s[1024];
    const int CH = (NNODES + 1023) / 1024;  // 49
    int t = threadIdx.x;
    int beg = t * CH;
    int end = min(NNODES, beg + CH);
    int mysum = 0;
    for (int i = beg; i < end; i++) mysum += g_cursor[i];
    s[t] = mysum;
    __syncthreads();
    for (int off = 1; off < 1024; off <<= 1) {
        int v = (t >= off) ? s[t - off] : 0;
        __syncthreads();
        s[t] += v;
        __syncthreads();
    }
    int run = s[t] - mysum;  // exclusive prefix
    for (int i = beg; i < end; i++) {
        g_rowptr[i] = run;
        run += g_cursor[i];
    }
    if (t == 1023) g_rowptr[NNODES] = s[1023];
}

__global__ void k_reset_cursor() {
    for (int i = blockIdx.x * blockDim.x + threadIdx.x; i <= NNODES;
         i += gridDim.x * blockDim.x)
        g_cursor[i] = g_rowptr[i];
}

__global__ void k_scatter(const int* __restrict__ row, const int* __restrict__ col,
                          const float* __restrict__ vals) {
    for (int e = blockIdx.x * blockDim.x + threadIdx.x; e < NEDGES;
         e += gridDim.x * blockDim.x) {
        int p = atomicAdd(&g_cursor[row[e]], 1);
        g_cols[p] = col[e];
        g_vals[p] = vals[e];
    }
}

// ---------------- fp32 tiled SGEMM (FFMA2 inner): C = op(A) @ B -----------------
// op(A) = mixA ? 0.5*(A + Amix) : A.  Optional relu on store.
__global__ void __launch_bounds__(256)
k_sgemm(const float* __restrict__ A, const float* __restrict__ Amix,
        const float* __restrict__ B, float* __restrict__ C,
        int M, int N, int K, int mixA, int reluOut) {
    const int BM = 128, BN = 128, BK = 8;
    __shared__ float As[BK][BM];
    __shared__ float Bs[BK][BN];
    int tid = threadIdx.x;
    int tx = tid & 15, ty = tid >> 4;
    int rowBase = blockIdx.y * BM, colBase = blockIdx.x * BN;

    float2 acc2[8][4];
#pragma unroll
    for (int i = 0; i < 8; i++)
#pragma unroll
        for (int j = 0; j < 4; j++) acc2[i][j] = make_float2(0.f, 0.f);

    int aRow = tid >> 1;
    int aK = (tid & 1) * 4;
    int bK = tid >> 5;
    int bCol = (tid & 31) * 4;
    int gr = rowBase + aRow;

    for (int k0 = 0; k0 < K; k0 += BK) {
        // A tile (zero-pad out-of-range)
        {
            int gk = k0 + aK;
            float4 va = make_float4(0.f, 0.f, 0.f, 0.f);
            if (gr < M && gk < K) {
                va = *(const float4*)(A + (size_t)gr * K + gk);
                if (mixA) {
                    float4 w = *(const float4*)(Amix + (size_t)gr * K + gk);
                    va.x = 0.5f * (va.x + w.x);
                    va.y = 0.5f * (va.y + w.y);
                    va.z = 0.5f * (va.z + w.z);
                    va.w = 0.5f * (va.w + w.w);
                }
            }
            As[aK + 0][aRow] = va.x;
            As[aK + 1][aRow] = va.y;
            As[aK + 2][aRow] = va.z;
            As[aK + 3][aRow] = va.w;
        }
        // B tile
        {
            int gk = k0 + bK;
            int gc = colBase + bCol;
            float4 vb = make_float4(0.f, 0.f, 0.f, 0.f);
            if (gk < K) {
                if (gc + 3 < N) {
                    vb = *(const float4*)(B + (size_t)gk * N + gc);
                } else {
                    if (gc + 0 < N) vb.x = B[(size_t)gk * N + gc + 0];
                    if (gc + 1 < N) vb.y = B[(size_t)gk * N + gc + 1];
                    if (gc + 2 < N) vb.z = B[(size_t)gk * N + gc + 2];
                }
            }
            *(float4*)&Bs[bK][bCol] = vb;
        }
        __syncthreads();
#pragma unroll
        for (int kk = 0; kk < BK; kk++) {
            float4 a0 = *(const float4*)&As[kk][ty * 8];
            float4 a1 = *(const float4*)&As[kk][ty * 8 + 4];
            float4 b0 = *(const float4*)&Bs[kk][tx * 8];
            float4 b1 = *(const float4*)&Bs[kk][tx * 8 + 4];
            float2 bb[4];
            bb[0] = make_float2(b0.x, b0.y);
            bb[1] = make_float2(b0.z, b0.w);
            bb[2] = make_float2(b1.x, b1.y);
            bb[3] = make_float2(b1.z, b1.w);
            float av[8] = {a0.x, a0.y, a0.z, a0.w, a1.x, a1.y, a1.z, a1.w};
#pragma unroll
            for (int i = 0; i < 8; i++) {
                float2 ai = make_float2(av[i], av[i]);
#pragma unroll
                for (int j = 0; j < 4; j++) ffma2(acc2[i][j], ai, bb[j]);
            }
        }
        __syncthreads();
    }
#pragma unroll
    for (int i = 0; i < 8; i++) {
        int r = rowBase + ty * 8 + i;
        if (r >= M) continue;
        float* crow = C + (size_t)r * N;
        float vals[8] = {acc2[i][0].x, acc2[i][0].y, acc2[i][1].x, acc2[i][1].y,
                         acc2[i][2].x, acc2[i][2].y, acc2[i][3].x, acc2[i][3].y};
#pragma unroll
        for (int j = 0; j < 8; j++) {
            int c = colBase + tx * 8 + j;
            if (c < N) {
                float v = vals[j];
                if (reluOut) v = fmaxf(v, 0.f);
                crow[c] = v;
            }
        }
    }
}

// ---------------- SpMM width-500: out[r,:] = sum_e val * in[col,:] ---------------
__global__ void __launch_bounds__(128)
k_spmm_w500(const float* __restrict__ Min, float* __restrict__ Mout, int relu) {
    const int W = 500;
    int r = blockIdx.x;
    int t = threadIdx.x;  // 128
    int start = g_rowptr[r], end = g_rowptr[r + 1];
    float a0 = 0.f, a1 = 0.f, a2 = 0.f, a3 = 0.f;
    __shared__ int scol[128];
    __shared__ float sval[128];
    for (int e0 = start; e0 < end; e0 += 128) {
        int n = min(128, end - e0);
        if (t < n) {
            scol[t] = g_cols[e0 + t];
            sval[t] = g_vals[e0 + t];
        }
        __syncthreads();
        for (int i = 0; i < n; i++) {
            const float* p = Min + (size_t)scol[i] * W;
            float v = sval[i];
            a0 += v * p[t];
            a1 += v * p[t + 128];
            a2 += v * p[t + 256];
            if (t < 116) a3 += v * p[t + 384];
        }
        __syncthreads();
    }
    if (relu) {
        a0 = fmaxf(a0, 0.f);
        a1 = fmaxf(a1, 0.f);
        a2 = fmaxf(a2, 0.f);
        a3 = fmaxf(a3, 0.f);
    }
    float* o = Mout + (size_t)r * W;
    o[t] = a0;
    o[t + 128] = a1;
    o[t + 256] = a2;
    if (t < 116) o[t + 384] = a3;
}

// ---------------- SpMM width-10 (thread per row) --------------------------------
__global__ void k_spmm_w10(const float* __restrict__ Min, float* __restrict__ Mout,
                           int relu) {
    int r = blockIdx.x * blockDim.x + threadIdx.x;
    if (r >= NNODES) return;
    float acc[10];
#pragma unroll
    for (int j = 0; j < 10; j++) acc[j] = 0.f;
    int start = g_rowptr[r], end = g_rowptr[r + 1];
    for (int e = start; e < end; e++) {
        int c = g_cols[e];
        float v = g_vals[e];
        const float2* p = (const float2*)(Min + (size_t)c * 10);
#pragma unroll
        for (int j = 0; j < 5; j++) {
            float2 x = p[j];
            acc[2 * j + 0] += v * x.x;
            acc[2 * j + 1] += v * x.y;
        }
    }
    float* o = Mout + (size_t)r * 10;
#pragma unroll
    for (int j = 0; j < 10; j++) o[j] = relu ? fmaxf(acc[j], 0.f) : acc[j];
}

// ---------------- elementwise mix: O = 0.5*(A+B), n multiple of 4 ----------------
__global__ void k_mix(const float* __restrict__ A, const float* __restrict__ B,
                      float* __restrict__ O, int n4) {
    for (int i = blockIdx.x * blockDim.x + threadIdx.x; i < n4;
         i += gridDim.x * blockDim.x) {
        float4 a = ((const float4*)A)[i];
        float4 b = ((const float4*)B)[i];
        float4 o;
        o.x = 0.5f * (a.x + b.x);
        o.y = 0.5f * (a.y + b.y);
        o.z = 0.5f * (a.z + b.z);
        o.w = 0.5f * (a.w + b.w);
        ((float4*)O)[i] = o;
    }
}

// ---------------- thin GEMM layer4: (0.5*(H+tra3))[50000,2000] @ W4[2000,10] -----
__global__ void __launch_bounds__(256)
k_gemm_thin(const float* __restrict__ Hin, const float* __restrict__ Tmix,
            const float* __restrict__ W4, float* __restrict__ Mout) {
    const int K = 2000, CHUNK = 1000;
    __shared__ float Ws[CHUNK * 10];  // 40 KB
    int tid = threadIdx.x;
    int r = blockIdx.x * 256 + tid;
    float acc[10];
#pragma unroll
    for (int j = 0; j < 10; j++) acc[j] = 0.f;
    for (int k0 = 0; k0 < K; k0 += CHUNK) {
        __syncthreads();
        for (int i = tid; i < CHUNK * 10; i += 256) Ws[i] = W4[k0 * 10 + i];
        __syncthreads();
        if (r < NNODES) {
            const float* hrow = Hin + (size_t)r * K + k0;
            const float* trow = Tmix + (size_t)r * K + k0;
            for (int k = 0; k < CHUNK; k += 4) {
                float4 h = *(const float4*)(hrow + k);
                float4 t = *(const float4*)(trow + k);
                float a0 = 0.5f * (h.x + t.x);
                float a1 = 0.5f * (h.y + t.y);
                float a2 = 0.5f * (h.z + t.z);
                float a3 = 0.5f * (h.w + t.w);
#pragma unroll
                for (int j = 0; j < 10; j++)
                    acc[j] += a0 * Ws[(k + 0) * 10 + j] + a1 * Ws[(k + 1) * 10 + j] +
                              a2 * Ws[(k + 2) * 10 + j] + a3 * Ws[(k + 3) * 10 + j];
            }
        }
    }
    if (r < NNODES) {
        float* o = Mout + (size_t)r * 10;
#pragma unroll
        for (int j = 0; j < 10; j++) o[j] = acc[j];
    }
}

// ---------------- tiny GEMM layer5: (0.5*(H+z))[*,10] @ W5[10,10] ----------------
__global__ void k_gemm5(const float* __restrict__ Hin, const float* __restrict__ Zmix,
                        const float* __restrict__ W5, float* __restrict__ Mout) {
    __shared__ float Ws[100];
    int t = threadIdx.x;
    if (t < 100) Ws[t] = W5[t];
    __syncthreads();
    int r = blockIdx.x * blockDim.x + t;
    if (r >= NNODES) return;
    float a[10];
#pragma unroll
    for (int k = 0; k < 10; k++)
        a[k] = 0.5f * (Hin[(size_t)r * 10 + k] + Zmix[(size_t)r * 10 + k]);
    float* o = Mout + (size_t)r * 10;
#pragma unroll
    for (int j = 0; j < 10; j++) {
        float s = 0.f;
#pragma unroll
        for (int k = 0; k < 10; k++) s += a[k] * Ws[k * 10 + j];
        o[j] = s;
    }
}

// ---------------- row softmax over width 10 --------------------------------------
__global__ void k_softmax(const float* __restrict__ S, float* __restrict__ out) {
    int r = blockIdx.x * blockDim.x + threadIdx.x;
    if (r >= NNODES) return;
    float v[10];
    float m = -1e30f;
#pragma unroll
    for (int j = 0; j < 10; j++) {
        v[j] = S[(size_t)r * 10 + j];
        m = fmaxf(m, v[j]);
    }
    float sum = 0.f;
#pragma unroll
    for (int j = 0; j < 10; j++) {
        v[j] = expf(v[j] - m);
        sum += v[j];
    }
    float inv = 1.f / sum;
#pragma unroll
    for (int j = 0; j < 10; j++) out[(size_t)r * 10 + j] = v[j] * inv;
}

// ---------------- launch ---------------------------------------------------------
extern "C" void kernel_launch(void* const* d_in, const int* in_sizes, int n_in,
                              void* d_out, int out_size) {
    const float* x    = (const float*)d_in[0];   // [50000,512]
    const float* tra1 = (const float*)d_in[1];   // [50000,500]
    const float* tra2 = (const float*)d_in[2];   // [50000,500]
    const float* tra3 = (const float*)d_in[3];   // [50000,2000]
    const float* z    = (const float*)d_in[4];   // [50000,10]
    const float* evals = (const float*)d_in[5];  // [E]
    const int*   row  = (const int*)d_in[6];     // [E]
    const int*   col  = (const int*)d_in[7];     // [E]
    const float* W1 = (const float*)d_in[8];     // [512,500]
    const float* W2 = (const float*)d_in[9];     // [500,500]
    const float* W3 = (const float*)d_in[10];    // [500,2000]
    const float* W4 = (const float*)d_in[11];    // [2000,10]
    const float* W5 = (const float*)d_in[12];    // [10,10]
    float* out = (float*)d_out;

    float *bufA, *bufB, *bufS0, *bufS1;
    cudaGetSymbolAddress((void**)&bufA, g_bufA);
    cudaGetSymbolAddress((void**)&bufB, g_bufB);
    cudaGetSymbolAddress((void**)&bufS0, g_bufS0);
    cudaGetSymbolAddress((void**)&bufS1, g_bufS1);

    // CSR build
    k_zero_counts<<<64, 256>>>();
    k_hist<<<2048, 256>>>(row);
    k_scan<<<1, 1024>>>();
    k_reset_cursor<<<64, 256>>>();
    k_scatter<<<2048, 256>>>(row, col, evals);

    dim3 g500(4, 391), g2000(16, 391);

    // L1: B1 = x @ W1 ; H1 = relu(spmm(B1))
    k_sgemm<<<g500, 256>>>(x, x, W1, bufA, NNODES, 500, 512, 0, 0);
    k_spmm_w500<<<NNODES, 128>>>(bufA, bufB, 1);

    // L2: B2 = (0.5*(H1+tra1)) @ W2 ; H2 = relu(spmm(B2))
    k_sgemm<<<g500, 256>>>(bufB, tra1, W2, bufA, NNODES, 500, 500, 1, 0);
    k_spmm_w500<<<NNODES, 128>>>(bufA, bufB, 1);

    // L3 (reordered: spmm first at width 500, then GEMM to 2000):
    // M3 = 0.5*(H2+tra2) ; S3 = spmm(M3) ; H3 = relu(S3 @ W3)
    k_mix<<<2048, 256>>>(bufB, tra2, bufA, NNODES * 500 / 4);
    k_spmm_w500<<<NNODES, 128>>>(bufA, bufB, 0);
    k_sgemm<<<g2000, 256>>>(bufB, bufB, W3, bufA, NNODES, 2000, 500, 0, 1);

    // L4: B4 = (0.5*(H3+tra3)) @ W4 ; H4 = relu(spmm10(B4))
    k_gemm_thin<<<(NNODES + 255) / 256, 256>>>(bufA, tra3, W4, bufS0);
    k_spmm_w10<<<(NNODES + 255) / 256, 256>>>(bufS0, bufS1, 1);

    // L5: B5 = (0.5*(H4+z)) @ W5 ; S5 = spmm10(B5) ; out = softmax(S5)
    k_gemm5<<<(NNODES + 255) / 256, 256>>>(bufS1, z, W5, bufS0);
    k_spmm_w10<<<(NNODES + 255) / 256, 256>>>(bufS0, bufS1, 0);
    k_softmax<<<(NNODES + 255) / 256, 256>>>(bufS1, out);
}